// round 3
// baseline (speedup 1.0000x reference)
#include <cuda_runtime.h>
#include <math.h>

#define N_TOK 8192
#define DIM   4096
#define NEXP  16
#define TPB   256
#define NWARP 8
#define TOK_PER_BLK 32
#define KSLICE (DIM / NWARP)   /* 512 per warp */
#define GCHUNK 128             /* gate k-chunk staged in smem per warp */
#define XTILE  16              /* x k-tile per pipeline stage */
#define XSTR   34              /* 32 tokens + pad (even -> 8B aligned pairs) */
#define NTILES (KSLICE / XTILE)  /* 32 */

#define SMEM_GS   (NWARP * GCHUNK * NEXP)          /* 16384 f */
#define SMEM_XS   (NWARP * XTILE * XSTR)           /*  4352 f */
#define SMEM_PART (NWARP * TOK_PER_BLK * NEXP)     /*  4096 f */
#define SMEM_LG   (TOK_PER_BLK * NEXP)             /*   512 f */
#define SMEM_FLOATS (SMEM_GS + SMEM_XS + SMEM_PART + SMEM_LG)
#define SMEM_BYTES (SMEM_FLOATS * 4)               /* 101376 B -> 2 CTAs/SM */

__device__ __forceinline__ void ldg_xtile(const float* __restrict__ x,
                                          int tokBase, int kpos, int l,
                                          float4 v[4])
{
#pragma unroll
    for (int i = 0; i < 4; i++) {
        int r = i * 8 + (l >> 2);
        int q = l & 3;
        v[i] = *(const float4*)(x + (size_t)(tokBase + r) * DIM + kpos + q * 4);
    }
}

__device__ __forceinline__ void sts_xtile(float* xs_w, int l, const float4 v[4])
{
#pragma unroll
    for (int i = 0; i < 4; i++) {
        int r = i * 8 + (l >> 2);
        int q = l & 3;
        xs_w[(q * 4 + 0) * XSTR + r] = v[i].x;
        xs_w[(q * 4 + 1) * XSTR + r] = v[i].y;
        xs_w[(q * 4 + 2) * XSTR + r] = v[i].z;
        xs_w[(q * 4 + 3) * XSTR + r] = v[i].w;
    }
}

__device__ __forceinline__ void stage_gate(const float* __restrict__ gate,
                                           float* gs_w, int kbase, int l)
{
    __syncwarp();
    const float4* gsrc = (const float4*)(gate + (size_t)kbase * NEXP);
    float4* gdst = (float4*)gs_w;
#pragma unroll
    for (int i = 0; i < (GCHUNK * NEXP) / (32 * 4); i++) {   // 16 iters
        gdst[i * 32 + l] = gsrc[i * 32 + l];
    }
    __syncwarp();
}

__global__ void __launch_bounds__(TPB, 2)
router_kernel(const float* __restrict__ x,
              const float* __restrict__ gate,
              float* __restrict__ out,
              int out_size)
{
    extern __shared__ float smem[];
    float* gs   = smem;                 // [NWARP][GCHUNK][16]
    float* xs   = gs + SMEM_GS;         // [NWARP][XTILE][XSTR] transposed x tile
    float* part = xs + SMEM_XS;         // [NWARP][32][16]
    float* lg   = part + SMEM_PART;     // [32][16]

    const int tid = threadIdx.x;
    const int w   = tid >> 5;
    const int l   = tid & 31;
    const int tokBase = blockIdx.x * TOK_PER_BLK;

    float* gs_w = gs + w * (GCHUNK * NEXP);
    float* xs_w = xs + w * (XTILE * XSTR);
    const int kw = w * KSLICE;

    const int tp  = l & 15;        // token pair: tokens 2tp, 2tp+1
    const int eb8 = (l >> 4) * 8;  // expert float base: experts eb8..eb8+7

    // acc[j]: f32x2 over expert pair (eb8/2 + j); acc0 = token 2tp, acc1 = 2tp+1
    unsigned long long acc0[4], acc1[4];
#pragma unroll
    for (int i = 0; i < 4; i++) { acc0[i] = 0ull; acc1[i] = 0ull; }

    float4 va[4], vb[4];

    // prologue: gate chunk 0 + x tile 0
    stage_gate(gate, gs_w, kw, l);
    ldg_xtile(x, tokBase, kw, l, va);

    for (int t = 0; t < NTILES; t++) {
        // prefetch next x tile into registers (overlaps with this tile's compute)
        if (t + 1 < NTILES)
            ldg_xtile(x, tokBase, kw + (t + 1) * XTILE, l, vb);

        __syncwarp();            // prev compute's xs reads done before overwrite
        sts_xtile(xs_w, l, va);
        __syncwarp();

        // stage new gate chunk when crossing a GCHUNK boundary (t = 8,16,24)
        if ((t & 7) == 0 && t > 0)
            stage_gate(gate, gs_w, kw + (t >> 3) * GCHUNK, l);

        const int rowBase = (t & 7) * XTILE;   // gate row offset within chunk

#pragma unroll
        for (int kk = 0; kk < XTILE; kk++) {
            float2 xv = *(const float2*)(xs_w + kk * XSTR + 2 * tp);
            unsigned long long xp0, xp1;
            asm("mov.b64 %0, {%1,%1};" : "=l"(xp0) : "f"(xv.x));
            asm("mov.b64 %0, {%1,%1};" : "=l"(xp1) : "f"(xv.y));

            const float* grow = gs_w + (rowBase + kk) * NEXP + eb8;
            ulonglong2 Ga = *(const ulonglong2*)(grow);       // experts eb8..eb8+3
            ulonglong2 Gb = *(const ulonglong2*)(grow + 4);   // experts eb8+4..eb8+7

            asm("fma.rn.f32x2 %0, %1, %2, %0;" : "+l"(acc0[0]) : "l"(xp0), "l"(Ga.x));
            asm("fma.rn.f32x2 %0, %1, %2, %0;" : "+l"(acc0[1]) : "l"(xp0), "l"(Ga.y));
            asm("fma.rn.f32x2 %0, %1, %2, %0;" : "+l"(acc0[2]) : "l"(xp0), "l"(Gb.x));
            asm("fma.rn.f32x2 %0, %1, %2, %0;" : "+l"(acc0[3]) : "l"(xp0), "l"(Gb.y));
            asm("fma.rn.f32x2 %0, %1, %2, %0;" : "+l"(acc1[0]) : "l"(xp1), "l"(Ga.x));
            asm("fma.rn.f32x2 %0, %1, %2, %0;" : "+l"(acc1[1]) : "l"(xp1), "l"(Ga.y));
            asm("fma.rn.f32x2 %0, %1, %2, %0;" : "+l"(acc1[2]) : "l"(xp1), "l"(Gb.x));
            asm("fma.rn.f32x2 %0, %1, %2, %0;" : "+l"(acc1[3]) : "l"(xp1), "l"(Gb.y));
        }

        // rotate prefetch buffer
#pragma unroll
        for (int i = 0; i < 4; i++) va[i] = vb[i];
    }

    // ---- per-warp partials: 8 experts x 2 tokens per lane ----
    {
        unsigned long long* p0 =
            (unsigned long long*)(part + (size_t)(w * TOK_PER_BLK + 2 * tp) * NEXP + eb8);
        unsigned long long* p1 =
            (unsigned long long*)(part + (size_t)(w * TOK_PER_BLK + 2 * tp + 1) * NEXP + eb8);
#pragma unroll
        for (int i = 0; i < 4; i++) { p0[i] = acc0[i]; p1[i] = acc1[i]; }
    }
    __syncthreads();

    // ---- reduce 8 warps: thread -> (token, 2 experts) ----
    {
        int tok = tid >> 3, e2 = (tid & 7) * 2;
        float2 s = make_float2(0.f, 0.f);
#pragma unroll
        for (int ww = 0; ww < NWARP; ww++) {
            float2 v = *(const float2*)(part + (size_t)(ww * TOK_PER_BLK + tok) * NEXP + e2);
            s.x += v.x; s.y += v.y;
        }
        *(float2*)(lg + tok * NEXP + e2) = s;
    }
    __syncthreads();

    // ---- top-2 + sigmoid + transposed score writes ----
    if (tid < TOK_PER_BLK) {
        int tok = tid;
        float v[NEXP];
#pragma unroll
        for (int e = 0; e < NEXP; e++) v[e] = lg[tok * NEXP + e];
        float v1 = -INFINITY, v2 = -INFINITY;
        int   i1 = -1,        i2 = -1;
#pragma unroll
        for (int e = 0; e < NEXP; e++) {
            float t = v[e];
            if (t > v1)      { v2 = v1; i2 = i1; v1 = t; i1 = e; }
            else if (t > v2) { v2 = t;  i2 = e; }
        }
        int gtok = tokBase + tok;
#pragma unroll
        for (int e = 0; e < NEXP; e++) {
            float sc = (e == i1 || e == i2) ? (1.0f / (1.0f + expf(-v[e]))) : 0.0f;
            out[(size_t)e * N_TOK + gtok] = sc;   // 32 consecutive tokens: coalesced
        }
    }

    // ---- token_indices (second output region), values as floats ----
    if (out_size >= 2 * NEXP * N_TOK) {
        int c  = tid & 31;
        int e0 = tid >> 5;                  // 0..7
        int gtok = tokBase + c;
        float fv = (float)gtok;
        out[(size_t)NEXP * N_TOK + (size_t)e0       * N_TOK + gtok] = fv;
        out[(size_t)NEXP * N_TOK + (size_t)(e0 + 8) * N_TOK + gtok] = fv;
    }
}

extern "C" void kernel_launch(void* const* d_in, const int* in_sizes, int n_in,
                              void* d_out, int out_size)
{
    const float* x    = (const float*)d_in[0];
    const float* gate = (const float*)d_in[1];
    float* out = (float*)d_out;

    cudaFuncSetAttribute(router_kernel,
                         cudaFuncAttributeMaxDynamicSharedMemorySize, SMEM_BYTES);

    dim3 grid(N_TOK / TOK_PER_BLK);   // 256 blocks, 2 CTAs/SM
    dim3 block(TPB);
    router_kernel<<<grid, block, SMEM_BYTES>>>(x, gate, out, out_size);
}